// round 2
// baseline (speedup 1.0000x reference)
#include <cuda_runtime.h>

// waspGridSpatialIntegral: input [B=64, 2, W=512, W=512] fp32.
//   out[:,0,:,:] = cumsum(in[:,0,:,:], axis=-1)  (along contiguous width)
//   out[:,1,:,:] = cumsum(in[:,1,:,:], axis=-2)  (along height, stride W)
//
// Pure HBM streaming: 268 MB total traffic, floor ~40 us.
// One fused launch:
//   blocks [0, 256)        : column scans, channel 1 (long-running -> lowest bid)
//   blocks [256, 256+32768): row scans, channel 0 (one block per row)

#define W      512
#define WW     (512 * 512)          // one plane
#define B      64
#define NROWS  (B * W)              // 32768 channel-0 rows
#define CTILES 4                    // 512 cols / 128 threads
#define NCOLB  (B * CTILES)         // 256 channel-1 blocks
#define UNR    16                   // column-loop batch depth (MLP per thread)

__global__ __launch_bounds__(128) void wasp_integral_kernel(
    const float* __restrict__ in, float* __restrict__ out)
{
    const int bid = blockIdx.x;
    const int tid = threadIdx.x;

    if (bid < NCOLB) {
        // ------- channel 1: column scan (cumsum along y, stride W) -------
        const int b    = bid >> 2;          // image
        const int tile = bid & 3;           // column tile
        const int col  = tile * 128 + tid;
        const float* src = in  + (size_t)(b * 2 + 1) * WW + col;
        float*       dst = out + (size_t)(b * 2 + 1) * WW + col;

        float acc = 0.0f;
        for (int r = 0; r < W; r += UNR) {
            // Phase 1: batch 16 independent loads (front-batched -> MLP 16)
            float v[UNR];
            #pragma unroll
            for (int i = 0; i < UNR; ++i)
                v[i] = src[(size_t)(r + i) * W];
            // Phase 2: serial accumulate + fire-and-forget stores
            #pragma unroll
            for (int i = 0; i < UNR; ++i) {
                acc += v[i];
                dst[(size_t)(r + i) * W] = acc;
            }
        }
    } else {
        // ------- channel 0: row scan (cumsum along x, contiguous) -------
        const int rowid = bid - NCOLB;      // 0 .. NROWS-1
        const int b     = rowid >> 9;
        const int y     = rowid & 511;
        const size_t base = (size_t)(b * 2) * WW + (size_t)y * W;

        const float4* src = reinterpret_cast<const float4*>(in + base);
        float4*       dst = reinterpret_cast<float4*>(out + base);

        float4 v = src[tid];
        v.y += v.x; v.z += v.y; v.w += v.z;   // local inclusive scan of 4

        const int lane = tid & 31;
        const int wid  = tid >> 5;

        float t = v.w;                         // warp scan of thread totals
        #pragma unroll
        for (int d = 1; d < 32; d <<= 1) {
            float n = __shfl_up_sync(0xFFFFFFFFu, t, d);
            if (lane >= d) t += n;
        }

        __shared__ float wsum[4];
        if (lane == 31) wsum[wid] = t;
        __syncthreads();

        float off = t - v.w;                   // intra-warp exclusive prefix
        #pragma unroll
        for (int w = 0; w < 3; ++w)
            if (wid > w) off += wsum[w];

        v.x += off; v.y += off; v.z += off; v.w += off;
        dst[tid] = v;
    }
}

extern "C" void kernel_launch(void* const* d_in, const int* in_sizes, int n_in,
                              void* d_out, int out_size)
{
    const float* in  = (const float*)d_in[0];
    float*       out = (float*)d_out;
    wasp_integral_kernel<<<NCOLB + NROWS, 128>>>(in, out);
}

// round 3
// speedup vs baseline: 1.1543x; 1.1543x over previous
#include <cuda_runtime.h>

// waspGridSpatialIntegral: input [B=64, 2, W=512, W=512] fp32.
//   out[:,0,:,:] = cumsum(in[:,0,:,:], axis=-1)  (contiguous width)
//   out[:,1,:,:] = cumsum(in[:,1,:,:], axis=-2)  (height, stride W)
//
// Pure HBM streaming: 268 MB traffic, floor ~38-41 us at achievable BW.
// One fused launch:
//   blocks [0, 256)        : column scans, channel 1 (long-running -> lowest bid)
//   blocks [256, 256+32768): row scans, channel 0 (one block per row)
//
// R3 change vs R2: column batch depth 16 -> 32 (chip-wide in-flight bytes for
// the column stream 2 MB -> 4 MB, above the BW*latency saturation product),
// plus evict-first streaming hints (no reuse anywhere).

#define W      512
#define WW     (512 * 512)
#define B      64
#define NROWS  (B * W)              // 32768 channel-0 rows
#define CTILES 4                    // 512 cols / 128 threads
#define NCOLB  (B * CTILES)         // 256 channel-1 blocks
#define UNR    32                   // column-loop batch depth (MLP per thread)

__global__ __launch_bounds__(128) void wasp_integral_kernel(
    const float* __restrict__ in, float* __restrict__ out)
{
    const int bid = blockIdx.x;
    const int tid = threadIdx.x;

    if (bid < NCOLB) {
        // ------- channel 1: column scan (cumsum along y, stride W) -------
        const int b    = bid >> 2;
        const int tile = bid & 3;
        const int col  = tile * 128 + tid;
        const float* src = in  + (size_t)(b * 2 + 1) * WW + col;
        float*       dst = out + (size_t)(b * 2 + 1) * WW + col;

        float acc = 0.0f;
        for (int r = 0; r < W; r += UNR) {
            // Phase 1: 32 independent loads, front-batched -> 32 lines in flight/warp
            float v[UNR];
            #pragma unroll
            for (int i = 0; i < UNR; ++i)
                v[i] = __ldcs(src + (size_t)(r + i) * W);
            // Phase 2: serial accumulate + fire-and-forget stores
            #pragma unroll
            for (int i = 0; i < UNR; ++i) {
                acc += v[i];
                __stcs(dst + (size_t)(r + i) * W, acc);
            }
        }
    } else {
        // ------- channel 0: row scan (cumsum along x, contiguous) -------
        const int rowid = bid - NCOLB;
        const int b     = rowid >> 9;
        const int y     = rowid & 511;
        const size_t base = (size_t)(b * 2) * WW + (size_t)y * W;

        const float4* src = reinterpret_cast<const float4*>(in + base);
        float4*       dst = reinterpret_cast<float4*>(out + base);

        float4 v = __ldcs(src + tid);
        v.y += v.x; v.z += v.y; v.w += v.z;   // local inclusive scan of 4

        const int lane = tid & 31;
        const int wid  = tid >> 5;

        float t = v.w;                         // warp scan of thread totals
        #pragma unroll
        for (int d = 1; d < 32; d <<= 1) {
            float n = __shfl_up_sync(0xFFFFFFFFu, t, d);
            if (lane >= d) t += n;
        }

        __shared__ float wsum[4];
        if (lane == 31) wsum[wid] = t;
        __syncthreads();

        float off = t - v.w;                   // intra-warp exclusive prefix
        #pragma unroll
        for (int w = 0; w < 3; ++w)
            if (wid > w) off += wsum[w];

        v.x += off; v.y += off; v.z += off; v.w += off;
        __stcs(dst + tid, v);
    }
}

extern "C" void kernel_launch(void* const* d_in, const int* in_sizes, int n_in,
                              void* d_out, int out_size)
{
    const float* in  = (const float*)d_in[0];
    float*       out = (float*)d_out;
    wasp_integral_kernel<<<NCOLB + NROWS, 128>>>(in, out);
}